// round 9
// baseline (speedup 1.0000x reference)
#include <cuda_runtime.h>

// Problem dims (fixed)
#define Bv 4
#define Nv 256
#define Dv 128
#define Mv 128
#define Cv 128
#define ROWS 1024

// Scratch (allocation-free: __device__ globals)
__device__ float g_pi[ROWS * Mv];       // 0.5*(h@W1a + b1)
__device__ float g_pj[ROWS * Mv];       // 0.5*(h@W1b)
__device__ float g_S0[ROWS * Mv];       // partial silu sum, j in [0,128)
__device__ float g_S1[ROWS * Mv];       // partial silu sum, j in [128,256)
__device__ float g_amask[ROWS];         // sum_{j!=i} adj
__device__ float g_denom[ROWS];         // max(sum_j adj, 1)

typedef unsigned long long ull;

// ---------------- packed f32x2 helpers ----------------
__device__ __forceinline__ ull pk2(float v) {
    ull r; asm("mov.b64 %0, {%1,%1};" : "=l"(r) : "f"(v)); return r;
}
__device__ __forceinline__ ull pkab(float a, float b) {
    ull r; asm("mov.b64 %0, {%1,%2};" : "=l"(r) : "f"(a), "f"(b)); return r;
}
__device__ __forceinline__ void fma2(ull& d, ull a, ull b) {
    asm("fma.rn.f32x2 %0, %1, %2, %0;" : "+l"(d) : "l"(a), "l"(b));
}
__device__ __forceinline__ ull add2(ull a, ull b) {
    ull r; asm("add.rn.f32x2 %0, %1, %2;" : "=l"(r) : "l"(a), "l"(b)); return r;
}
__device__ __forceinline__ void upk2(ull v, float& lo, float& hi) {
    asm("mov.b64 {%0,%1}, %2;" : "=f"(lo), "=f"(hi) : "l"(v));
}
__device__ __forceinline__ float tanh_ap(float x) {
    float t; asm("tanh.approx.f32 %0, %1;" : "=f"(t) : "f"(x)); return t;
}
// silu(2*xh) where xh = x/2:  xh*(1+tanh(xh))
__device__ __forceinline__ float silu_h(float xh) {
    return fmaf(xh, tanh_ap(xh), xh);
}
// packed silu_h on a f32x2 pair
__device__ __forceinline__ ull silu_h2(ull x2) {
    float x, y; upk2(x2, x, y);
    ull t2 = pkab(tanh_ap(x), tanh_ap(y));
    ull s2 = x2;
    fma2(s2, x2, t2);          // x2*t2 + x2
    return s2;
}

// ---------------------------------------------------------------------------
// K1: pre-GEMM, k-split 4. (1024x128)@(128x256), W=[W1a|W1b].
// 512 blocks x 256 thr = 4096 warps (~7/SMSP). Block = 2 rows x 256 cols.
// Thread: kseg = tid>>6 (32 k's), colquad = tid&63 (4 cols), both rows.
// h staged in smem pre-duplicated as f32x2 (no MOVs in hot loop).
// Partials reduced through smem (conflict-free slot layout).
// ---------------------------------------------------------------------------
__global__ __launch_bounds__(256) void k_pre(const float* __restrict__ h,
                                             const float* __restrict__ W1a,
                                             const float* __restrict__ W1b,
                                             const float* __restrict__ b1)
{
    __shared__ ull sH[2][Dv];        // pk2-duplicated h, 2 rows (2 KB)
    __shared__ ull sP[4][2][128];    // [kseg][row][slot] partials (8 KB)

    const int tid  = threadIdx.x;
    const int row0 = blockIdx.x << 1;

    // stage h (2 rows x 128), duplicated into both f32x2 halves
    {
        const int r = tid >> 7, k = tid & 127;
        sH[r][k] = pk2(__ldg(h + (row0 + r) * Dv + k));
    }
    __syncthreads();

    const int kseg = tid >> 6;         // 0..3
    const int q    = tid & 63;         // colquad
    const int c    = q << 2;           // col 0..252
    const float* __restrict__ Wp = (c < 128) ? (W1a + c) : (W1b + (c - 128));
    const int k0 = kseg << 5;

    ull a00 = 0, a01 = 0, a10 = 0, a11 = 0;
    #pragma unroll 8
    for (int kk = 0; kk < 32; ++kk) {
        const int k = k0 + kk;
        ulonglong2 w = __ldg((const ulonglong2*)(Wp + k * Mv));
        ull h0 = sH[0][k];
        ull h1 = sH[1][k];
        fma2(a00, h0, w.x); fma2(a01, h0, w.y);
        fma2(a10, h1, w.x); fma2(a11, h1, w.y);
    }
    // slot layout: a00 -> q, a01 -> 64+q (contiguous stores, no bank conflicts)
    sP[kseg][0][q]      = a00;
    sP[kseg][0][64 + q] = a01;
    sP[kseg][1][q]      = a10;
    sP[kseg][1][64 + q] = a11;
    __syncthreads();

    // reduce: 256 units = 2 rows x 128 col-pairs
    {
        const int r  = tid >> 7;
        const int cp = tid & 127;                    // col-pair index
        const int qq = cp >> 1;
        const int sl = (cp & 1) ? (64 + qq) : qq;    // slot for this col-pair
        ull s = add2(add2(sP[0][r][sl], sP[1][r][sl]),
                     add2(sP[2][r][sl], sP[3][r][sl]));
        float v0, v1; upk2(s, v0, v1);
        const int cc  = cp << 1;                     // global col (even)
        const int row = row0 + r;
        if (cc < 128) {
            float2 bb = __ldg((const float2*)(b1 + cc));
            *(float2*)(g_pi + row * Mv + cc) =
                make_float2(0.5f * (v0 + bb.x), 0.5f * (v1 + bb.y));
        } else {
            *(float2*)(g_pj + row * Mv + (cc - 128)) =
                make_float2(0.5f * v0, 0.5f * v1);
        }
    }
}

// ---------------------------------------------------------------------------
// K2: pairwise silu sum, j-split 2. 512 blocks x 256 thr = 4096 warps.
// u = bid*8+wid -> (ig = u>>2, m-half = (u>>1)&1, j-half = u&1).
// Lane owns 2 m's; 128 j per warp; packed f32x2 math, 2 tanh per j.
// ---------------------------------------------------------------------------
__global__ __launch_bounds__(256) void k_main(const float* __restrict__ adj)
{
    const int wid  = threadIdx.x >> 5;
    const int lane = threadIdx.x & 31;
    const int u    = (blockIdx.x << 3) + wid;        // 0..4095
    const int ig   = u >> 2;                         // 0..1023
    const int b    = ig >> 8;
    const int i    = ig & 255;
    const int mh   = (u >> 1) & 1;
    const int jh   = u & 1;
    const int m0   = (mh << 6) + (lane << 1);
    const float* __restrict__ adjr = adj + (size_t)ig * Nv;

    const float aii = __ldg(adjr + i);

    if ((u & 3) == 0) {      // one warp per row: adj reduction
        float4 s0 = __ldg((const float4*)adjr + lane);
        float4 s1 = __ldg((const float4*)adjr + 32 + lane);
        float rs = ((s0.x+s0.y)+(s0.z+s0.w)) + ((s1.x+s1.y)+(s1.z+s1.w));
        #pragma unroll
        for (int o = 16; o; o >>= 1) rs += __shfl_xor_sync(0xffffffffu, rs, o);
        if (lane == 0) {
            g_denom[ig] = fmaxf(rs, 1.0f);
            g_amask[ig] = rs - aii;
        }
    }

    const ull pi2 = *(const ull*)(g_pi + ig * Mv + m0);
    const float* __restrict__ pjb = g_pj + ((size_t)b * Nv) * Mv + m0;

    ull acc2 = 0;
    const int j0 = jh << 7;
    #pragma unroll 4
    for (int j = j0; j < j0 + 128; j += 4) {
        float4 av = __ldg((const float4*)adjr + (j >> 2));   // uniform across warp
        #pragma unroll
        for (int t = 0; t < 4; ++t) {
            float a = (t == 0) ? av.x : (t == 1) ? av.y : (t == 2) ? av.z : av.w;
            ull p2 = __ldg((const ull*)(pjb + (j + t) * Mv));
            ull s2 = silu_h2(add2(pi2, p2));
            fma2(acc2, pk2(a), s2);
        }
    }

    // subtract diagonal if i falls in this warp's j-range
    if ((i >> 7) == jh) {
        ull p2 = __ldg((const ull*)(pjb + i * Mv));
        ull s2 = silu_h2(add2(pi2, p2));
        fma2(acc2, pk2(-aii), s2);
    }

    float* dst = (jh == 0) ? g_S0 : g_S1;
    *(ull*)(dst + ig * Mv + m0) = acc2;
}

// ---------------------------------------------------------------------------
// K3: chained GEMM epilogue. 128 blocks x 512 thr, 8 rows/block.
// 4-way k-split; thread does 4 rows x 1 col-pair (f32x2 straight from gmem).
// ---------------------------------------------------------------------------
__global__ __launch_bounds__(512) void k_post(const float* __restrict__ W2,  const float* __restrict__ b2,
                                              const float* __restrict__ Wc1, const float* __restrict__ bc1,
                                              const float* __restrict__ Wc2, const float* __restrict__ bc2,
                                              float* __restrict__ out)
{
    __shared__ ull sIn[8][Mv];      // duplicated f32x2 packs of current rows
    __shared__ ull sP[4][8][64];    // k-split partial accumulators

    const int tid  = threadIdx.x;
    const int row0 = blockIdx.x << 3;
    const int kseg = tid >> 7;          // 0..3
    const int rowg = (tid >> 6) & 1;    // rows {rowg, +2, +4, +6}
    const int cp   = tid & 63;          // col pair
    const int rrow = tid >> 6;          // reduce: output row 0..7
    const int rc   = (tid & 63) << 1;   // reduce: output col (even)

    for (int idx = tid; idx < 8 * Mv; idx += 512)
        sIn[idx >> 7][idx & 127] =
            pk2(__ldg(g_S0 + row0 * Mv + idx) + __ldg(g_S1 + row0 * Mv + idx));
    __syncthreads();

    #pragma unroll 1
    for (int phase = 0; phase < 3; ++phase) {
        const float* W = (phase == 0) ? W2 : (phase == 1) ? Wc1 : Wc2;
        ull a0 = 0, a1 = 0, a2 = 0, a3 = 0;
        const ull* __restrict__ Wp = (const ull*)W + cp;
        #pragma unroll 8
        for (int kk = 0; kk < 32; ++kk) {
            const int k = (kseg << 5) + kk;
            ull wp = __ldg(Wp + (k << 6));
            fma2(a0, sIn[rowg    ][k], wp);
            fma2(a1, sIn[rowg + 2][k], wp);
            fma2(a2, sIn[rowg + 4][k], wp);
            fma2(a3, sIn[rowg + 6][k], wp);
        }
        sP[kseg][rowg    ][cp] = a0;
        sP[kseg][rowg + 2][cp] = a1;
        sP[kseg][rowg + 4][cp] = a2;
        sP[kseg][rowg + 6][cp] = a3;
        __syncthreads();

        float vx = 0.f, vy = 0.f;
        #pragma unroll
        for (int ks = 0; ks < 4; ++ks) {
            float px, py; upk2(sP[ks][rrow][tid & 63], px, py);
            vx += px; vy += py;
        }
        const int grow = row0 + rrow;
        if (phase == 0) {
            float am  = __ldg(g_amask + grow);
            float inv = __fdividef(1.0f, __ldg(g_denom + grow));
            float2 bb = __ldg((const float2*)(b2 + rc));
            sIn[rrow][rc]     = pk2(fmaf(bb.x, am, vx) * inv);
            sIn[rrow][rc + 1] = pk2(fmaf(bb.y, am, vy) * inv);
        } else if (phase == 1) {
            float2 bb = __ldg((const float2*)(bc1 + rc));
            sIn[rrow][rc]     = pk2(silu_h(0.5f * (vx + bb.x)));
            sIn[rrow][rc + 1] = pk2(silu_h(0.5f * (vy + bb.y)));
        } else {
            float2 bb = __ldg((const float2*)(bc2 + rc));
            *(float2*)(out + grow * Cv + rc) = make_float2(vx + bb.x, vy + bb.y);
        }
        __syncthreads();
    }
}

// ---------------------------------------------------------------------------
// Launch. Inputs: 0:h 1:adj 2:W1a 3:W1b 4:b1 5:W2 6:b2 7:Wc1 8:bc1 9:Wc2 10:bc2
// ---------------------------------------------------------------------------
extern "C" void kernel_launch(void* const* d_in, const int* in_sizes, int n_in,
                              void* d_out, int out_size)
{
    (void)in_sizes; (void)n_in; (void)out_size;
    const float* h   = (const float*)d_in[0];
    const float* adj = (const float*)d_in[1];

    k_pre <<<512, 256>>>(h, (const float*)d_in[2], (const float*)d_in[3],
                         (const float*)d_in[4]);
    k_main<<<512, 256>>>(adj);
    k_post<<<128, 512>>>((const float*)d_in[5], (const float*)d_in[6],
                         (const float*)d_in[7], (const float*)d_in[8],
                         (const float*)d_in[9], (const float*)d_in[10],
                         (float*)d_out);
}

// round 11
// speedup vs baseline: 1.5043x; 1.5043x over previous
#include <cuda_runtime.h>

// Problem dims (fixed)
#define Bv 4
#define Nv 256
#define Dv 128
#define Mv 128
#define Cv 128
#define ROWS 1024

// Scratch (allocation-free: __device__ globals)
__device__ float g_pi[ROWS * Mv];       // 0.5*(h@W1a + b1)
__device__ float g_pj[ROWS * Mv];       // 0.5*(h@W1b)
__device__ float g_S0[ROWS * Mv];       // partial silu sum, j in [0,128)
__device__ float g_S1[ROWS * Mv];       // partial silu sum, j in [128,256)
__device__ float g_amask[ROWS];         // sum_{j!=i} adj
__device__ float g_denom[ROWS];         // max(sum_j adj, 1)

typedef unsigned long long ull;

// ---------------- packed f32x2 helpers ----------------
__device__ __forceinline__ ull pk2(float v) {
    ull r; asm("mov.b64 %0, {%1,%1};" : "=l"(r) : "f"(v)); return r;
}
__device__ __forceinline__ ull pkab(float a, float b) {
    ull r; asm("mov.b64 %0, {%1,%2};" : "=l"(r) : "f"(a), "f"(b)); return r;
}
__device__ __forceinline__ void fma2(ull& d, ull a, ull b) {
    asm("fma.rn.f32x2 %0, %1, %2, %0;" : "+l"(d) : "l"(a), "l"(b));
}
__device__ __forceinline__ ull add2(ull a, ull b) {
    ull r; asm("add.rn.f32x2 %0, %1, %2;" : "=l"(r) : "l"(a), "l"(b)); return r;
}
__device__ __forceinline__ void upk2(ull v, float& lo, float& hi) {
    asm("mov.b64 {%0,%1}, %2;" : "=f"(lo), "=f"(hi) : "l"(v));
}
__device__ __forceinline__ float tanh_ap(float x) {
    float t; asm("tanh.approx.f32 %0, %1;" : "=f"(t) : "f"(x)); return t;
}
// silu(2*xh) where xh = x/2:  xh*(1+tanh(xh))
__device__ __forceinline__ float silu_h(float xh) {
    return fmaf(xh, tanh_ap(xh), xh);
}
// packed silu_h on a f32x2 pair
__device__ __forceinline__ ull silu_h2(ull x2) {
    float x, y; upk2(x2, x, y);
    ull t2 = pkab(tanh_ap(x), tanh_ap(y));
    ull s2 = x2;
    fma2(s2, x2, t2);          // x2*t2 + x2
    return s2;
}

// ---------------------------------------------------------------------------
// K1: pre-GEMM, k-split 4. (1024x128)@(128x256), W=[W1a|W1b].
// 512 blocks x 256 thr. Block = 2 rows x 256 cols. (unchanged from R9: 11.7us)
// ---------------------------------------------------------------------------
__global__ __launch_bounds__(256) void k_pre(const float* __restrict__ h,
                                             const float* __restrict__ W1a,
                                             const float* __restrict__ W1b,
                                             const float* __restrict__ b1)
{
    __shared__ ull sH[2][Dv];        // pk2-duplicated h, 2 rows
    __shared__ ull sP[4][2][128];    // [kseg][row][slot] partials

    const int tid  = threadIdx.x;
    const int row0 = blockIdx.x << 1;

    {
        const int r = tid >> 7, k = tid & 127;
        sH[r][k] = pk2(__ldg(h + (row0 + r) * Dv + k));
    }
    __syncthreads();

    const int kseg = tid >> 6;         // 0..3
    const int q    = tid & 63;         // colquad
    const int c    = q << 2;           // col 0..252
    const float* __restrict__ Wp = (c < 128) ? (W1a + c) : (W1b + (c - 128));
    const int k0 = kseg << 5;

    ull a00 = 0, a01 = 0, a10 = 0, a11 = 0;
    #pragma unroll 8
    for (int kk = 0; kk < 32; ++kk) {
        const int k = k0 + kk;
        ulonglong2 w = __ldg((const ulonglong2*)(Wp + k * Mv));
        ull h0 = sH[0][k];
        ull h1 = sH[1][k];
        fma2(a00, h0, w.x); fma2(a01, h0, w.y);
        fma2(a10, h1, w.x); fma2(a11, h1, w.y);
    }
    sP[kseg][0][q]      = a00;
    sP[kseg][0][64 + q] = a01;
    sP[kseg][1][q]      = a10;
    sP[kseg][1][64 + q] = a11;
    __syncthreads();

    {
        const int r  = tid >> 7;
        const int cp = tid & 127;
        const int qq = cp >> 1;
        const int sl = (cp & 1) ? (64 + qq) : qq;
        ull s = add2(add2(sP[0][r][sl], sP[1][r][sl]),
                     add2(sP[2][r][sl], sP[3][r][sl]));
        float v0, v1; upk2(s, v0, v1);
        const int cc  = cp << 1;
        const int row = row0 + r;
        if (cc < 128) {
            float2 bb = __ldg((const float2*)(b1 + cc));
            *(float2*)(g_pi + row * Mv + cc) =
                make_float2(0.5f * (v0 + bb.x), 0.5f * (v1 + bb.y));
        } else {
            *(float2*)(g_pj + row * Mv + (cc - 128)) =
                make_float2(0.5f * v0, 0.5f * v1);
        }
    }
}

// ---------------------------------------------------------------------------
// K2: pairwise silu sum, pj tile staged in SMEM.
// Block = one (b, m-half, j-half) combo x 8 i-rows. 512 blocks x 256 thr.
// Tile: 128 j x 64 m = 32 KB, loaded once per block (raw float2 == f32x2).
// Inner loop: LDS + 2 tanh + 3 f32x2 ops per j (MUFU-bound).
// ---------------------------------------------------------------------------
__global__ __launch_bounds__(256) void k_main(const float* __restrict__ adj)
{
    __shared__ ull sPj[128][32];     // [j_local][lane] = 2 m's  (32 KB)

    const int tid   = threadIdx.x;
    const int wid   = tid >> 5;
    const int lane  = tid & 31;
    const int combo = blockIdx.x >> 5;             // 0..15
    const int blkc  = blockIdx.x & 31;             // 0..31
    const int b     = combo >> 2;
    const int mh    = (combo >> 1) & 1;
    const int jh    = combo & 1;
    const int i     = (blkc << 3) + wid;           // 0..255
    const int ig    = (b << 8) + i;
    const int m0    = (mh << 6) + (lane << 1);
    const int j0    = jh << 7;
    const float* __restrict__ adjr = adj + (size_t)ig * Nv;

    // stage pj tile: 4096 ull, 256 threads -> 16 iters, coalesced 8B loads
    {
        const float* __restrict__ base =
            g_pj + ((size_t)((b << 8) + j0)) * Mv + (mh << 6);
        #pragma unroll
        for (int it = 0; it < 16; ++it) {
            const int idx = (it << 8) + tid;       // 0..4095
            const int jj  = idx >> 5;
            const int lp  = idx & 31;
            sPj[jj][lp] = __ldg((const ull*)(base + jj * Mv) + lp);
        }
    }

    const float aii = __ldg(adjr + i);

    if (combo == ((b << 2) | 0) && (combo & 3) == 0) { /* never both false path */ }
    if ((combo & 3) == 0) {      // one combo per b does the adj reductions
        float4 s0 = __ldg((const float4*)adjr + lane);
        float4 s1 = __ldg((const float4*)adjr + 32 + lane);
        float rs = ((s0.x+s0.y)+(s0.z+s0.w)) + ((s1.x+s1.y)+(s1.z+s1.w));
        #pragma unroll
        for (int o = 16; o; o >>= 1) rs += __shfl_xor_sync(0xffffffffu, rs, o);
        if (lane == 0) {
            g_denom[ig] = fmaxf(rs, 1.0f);
            g_amask[ig] = rs - aii;
        }
    }

    const ull pi2 = *(const ull*)(g_pi + ig * Mv + m0);
    __syncthreads();

    ull acc2 = 0;
    #pragma unroll 4
    for (int j = 0; j < 128; j += 4) {
        float4 av = __ldg((const float4*)adjr + ((j0 + j) >> 2));  // uniform
        #pragma unroll
        for (int t = 0; t < 4; ++t) {
            float a = (t == 0) ? av.x : (t == 1) ? av.y : (t == 2) ? av.z : av.w;
            ull p2 = sPj[j + t][lane];
            ull s2 = silu_h2(add2(pi2, p2));
            fma2(acc2, pk2(a), s2);
        }
    }

    // subtract diagonal if i falls in this block's j-range
    if ((i >> 7) == jh) {
        ull p2 = sPj[i & 127][lane];
        ull s2 = silu_h2(add2(pi2, p2));
        fma2(acc2, pk2(-aii), s2);
    }

    float* dst = (jh == 0) ? g_S0 : g_S1;
    *(ull*)(dst + ig * Mv + m0) = acc2;
}

// ---------------------------------------------------------------------------
// K3: chained GEMM epilogue. 128 blocks x 512 thr, 8 rows/block. (unchanged)
// ---------------------------------------------------------------------------
__global__ __launch_bounds__(512) void k_post(const float* __restrict__ W2,  const float* __restrict__ b2,
                                              const float* __restrict__ Wc1, const float* __restrict__ bc1,
                                              const float* __restrict__ Wc2, const float* __restrict__ bc2,
                                              float* __restrict__ out)
{
    __shared__ ull sIn[8][Mv];      // duplicated f32x2 packs of current rows
    __shared__ ull sP[4][8][64];    // k-split partial accumulators

    const int tid  = threadIdx.x;
    const int row0 = blockIdx.x << 3;
    const int kseg = tid >> 7;          // 0..3
    const int rowg = (tid >> 6) & 1;    // rows {rowg, +2, +4, +6}
    const int cp   = tid & 63;          // col pair
    const int rrow = tid >> 6;          // reduce: output row 0..7
    const int rc   = (tid & 63) << 1;   // reduce: output col (even)

    for (int idx = tid; idx < 8 * Mv; idx += 512)
        sIn[idx >> 7][idx & 127] =
            pk2(__ldg(g_S0 + row0 * Mv + idx) + __ldg(g_S1 + row0 * Mv + idx));
    __syncthreads();

    #pragma unroll 1
    for (int phase = 0; phase < 3; ++phase) {
        const float* W = (phase == 0) ? W2 : (phase == 1) ? Wc1 : Wc2;
        ull a0 = 0, a1 = 0, a2 = 0, a3 = 0;
        const ull* __restrict__ Wp = (const ull*)W + cp;
        #pragma unroll 8
        for (int kk = 0; kk < 32; ++kk) {
            const int k = (kseg << 5) + kk;
            ull wp = __ldg(Wp + (k << 6));
            fma2(a0, sIn[rowg    ][k], wp);
            fma2(a1, sIn[rowg + 2][k], wp);
            fma2(a2, sIn[rowg + 4][k], wp);
            fma2(a3, sIn[rowg + 6][k], wp);
        }
        sP[kseg][rowg    ][cp] = a0;
        sP[kseg][rowg + 2][cp] = a1;
        sP[kseg][rowg + 4][cp] = a2;
        sP[kseg][rowg + 6][cp] = a3;
        __syncthreads();

        float vx = 0.f, vy = 0.f;
        #pragma unroll
        for (int ks = 0; ks < 4; ++ks) {
            float px, py; upk2(sP[ks][rrow][tid & 63], px, py);
            vx += px; vy += py;
        }
        const int grow = row0 + rrow;
        if (phase == 0) {
            float am  = __ldg(g_amask + grow);
            float inv = __fdividef(1.0f, __ldg(g_denom + grow));
            float2 bb = __ldg((const float2*)(b2 + rc));
            sIn[rrow][rc]     = pk2(fmaf(bb.x, am, vx) * inv);
            sIn[rrow][rc + 1] = pk2(fmaf(bb.y, am, vy) * inv);
        } else if (phase == 1) {
            float2 bb = __ldg((const float2*)(bc1 + rc));
            sIn[rrow][rc]     = pk2(silu_h(0.5f * (vx + bb.x)));
            sIn[rrow][rc + 1] = pk2(silu_h(0.5f * (vy + bb.y)));
        } else {
            float2 bb = __ldg((const float2*)(bc2 + rc));
            *(float2*)(out + grow * Cv + rc) = make_float2(vx + bb.x, vy + bb.y);
        }
        __syncthreads();
    }
}

// ---------------------------------------------------------------------------
// Launch. Inputs: 0:h 1:adj 2:W1a 3:W1b 4:b1 5:W2 6:b2 7:Wc1 8:bc1 9:Wc2 10:bc2
// ---------------------------------------------------------------------------
extern "C" void kernel_launch(void* const* d_in, const int* in_sizes, int n_in,
                              void* d_out, int out_size)
{
    (void)in_sizes; (void)n_in; (void)out_size;
    const float* h   = (const float*)d_in[0];
    const float* adj = (const float*)d_in[1];

    k_pre <<<512, 256>>>(h, (const float*)d_in[2], (const float*)d_in[3],
                         (const float*)d_in[4]);
    k_main<<<512, 256>>>(adj);
    k_post<<<128, 512>>>((const float*)d_in[5], (const float*)d_in[6],
                         (const float*)d_in[7], (const float*)d_in[8],
                         (const float*)d_in[9], (const float*)d_in[10],
                         (float*)d_out);
}

// round 12
// speedup vs baseline: 1.6039x; 1.0662x over previous
#include <cuda_runtime.h>

// Problem dims (fixed)
#define Bv 4
#define Nv 256
#define Dv 128
#define Mv 128
#define Cv 128
#define ROWS 1024

// Scratch (allocation-free: __device__ globals)
__device__ float g_pi[ROWS * Mv];       // 0.5*(h@W1a + b1)
__device__ float g_pj[ROWS * Mv];       // 0.5*(h@W1b)
__device__ float g_S0[ROWS * Mv];       // partial silu sum, j in [0,128)
__device__ float g_S1[ROWS * Mv];       // partial silu sum, j in [128,256)
__device__ float g_amask[ROWS];         // sum_{j!=i} adj
__device__ float g_denom[ROWS];         // max(sum_j adj, 1)

typedef unsigned long long ull;

// ---------------- packed f32x2 helpers ----------------
__device__ __forceinline__ ull pk2(float v) {
    ull r; asm("mov.b64 %0, {%1,%1};" : "=l"(r) : "f"(v)); return r;
}
__device__ __forceinline__ ull pkab(float a, float b) {
    ull r; asm("mov.b64 %0, {%1,%2};" : "=l"(r) : "f"(a), "f"(b)); return r;
}
__device__ __forceinline__ void fma2(ull& d, ull a, ull b) {
    asm("fma.rn.f32x2 %0, %1, %2, %0;" : "+l"(d) : "l"(a), "l"(b));
}
__device__ __forceinline__ ull add2(ull a, ull b) {
    ull r; asm("add.rn.f32x2 %0, %1, %2;" : "=l"(r) : "l"(a), "l"(b)); return r;
}
__device__ __forceinline__ void upk2(ull v, float& lo, float& hi) {
    asm("mov.b64 {%0,%1}, %2;" : "=f"(lo), "=f"(hi) : "l"(v));
}
__device__ __forceinline__ float tanh_ap(float x) {
    float t; asm("tanh.approx.f32 %0, %1;" : "=f"(t) : "f"(x)); return t;
}
// silu(2*xh) where xh = x/2:  xh*(1+tanh(xh))
__device__ __forceinline__ float silu_h(float xh) {
    return fmaf(xh, tanh_ap(xh), xh);
}
// packed silu_h on a f32x2 pair
__device__ __forceinline__ ull silu_h2(ull x2) {
    float x, y; upk2(x2, x, y);
    ull t2 = pkab(tanh_ap(x), tanh_ap(y));
    ull s2 = x2;
    fma2(s2, x2, t2);          // x2*t2 + x2
    return s2;
}

// ---------------------------------------------------------------------------
// K1: pre-GEMM, k-split 4, 4 rows/block. (1024x128)@(128x256), W=[W1a|W1b].
// 256 blocks x 256 thr. Halves per-block W re-reads vs R9 (32 MB L2 total).
// Thread: kseg = tid>>6 (32 k's), colquad = tid&63 (4 cols), 4 rows.
// ---------------------------------------------------------------------------
__global__ __launch_bounds__(256) void k_pre(const float* __restrict__ h,
                                             const float* __restrict__ W1a,
                                             const float* __restrict__ W1b,
                                             const float* __restrict__ b1)
{
    __shared__ ull sH[4][Dv];        // pk2-duplicated h, 4 rows (4 KB)
    __shared__ ull sP[4][4][128];    // [kseg][row][slot] partials (16 KB)

    const int tid  = threadIdx.x;
    const int row0 = blockIdx.x << 2;

    // stage h (4 rows x 128), duplicated into both f32x2 halves
    #pragma unroll
    for (int it = 0; it < 2; ++it) {
        const int idx = (it << 8) + tid;
        sH[idx >> 7][idx & 127] = pk2(__ldg(h + (row0 + (idx >> 7)) * Dv + (idx & 127)));
    }
    __syncthreads();

    const int kseg = tid >> 6;         // 0..3
    const int q    = tid & 63;         // colquad
    const int c    = q << 2;           // col 0..252
    const float* __restrict__ Wp = (c < 128) ? (W1a + c) : (W1b + (c - 128));
    const int k0 = kseg << 5;

    ull acc[4][2] = {};
    #pragma unroll 8
    for (int kk = 0; kk < 32; ++kk) {
        const int k = k0 + kk;
        ulonglong2 w = __ldg((const ulonglong2*)(Wp + k * Mv));
        #pragma unroll
        for (int r = 0; r < 4; ++r) {
            ull hr = sH[r][k];
            fma2(acc[r][0], hr, w.x);
            fma2(acc[r][1], hr, w.y);
        }
    }
    #pragma unroll
    for (int r = 0; r < 4; ++r) {
        sP[kseg][r][q]      = acc[r][0];
        sP[kseg][r][64 + q] = acc[r][1];
    }
    __syncthreads();

    // reduce: 512 units = 4 rows x 128 col-pairs, 2 iters
    #pragma unroll
    for (int it = 0; it < 2; ++it) {
        const int o  = (it << 8) + tid;
        const int r  = o >> 7;
        const int cp = o & 127;
        const int qq = cp >> 1;
        const int sl = (cp & 1) ? (64 + qq) : qq;
        ull s = add2(add2(sP[0][r][sl], sP[1][r][sl]),
                     add2(sP[2][r][sl], sP[3][r][sl]));
        float v0, v1; upk2(s, v0, v1);
        const int cc  = cp << 1;
        const int row = row0 + r;
        if (cc < 128) {
            float2 bb = __ldg((const float2*)(b1 + cc));
            *(float2*)(g_pi + row * Mv + cc) =
                make_float2(0.5f * (v0 + bb.x), 0.5f * (v1 + bb.y));
        } else {
            *(float2*)(g_pj + row * Mv + (cc - 128)) =
                make_float2(0.5f * v0, 0.5f * v1);
        }
    }
}

// ---------------------------------------------------------------------------
// K2: pairwise silu sum, full 128-m pj tile in SMEM (64 KB dynamic).
// Block = (b, j-half) x 8 i-rows. 256 blocks x 256 thr. Warp = one i-row,
// lane owns 4 m's via one LDS.128 per j. Tile is a contiguous 64 KB region.
// ---------------------------------------------------------------------------
__global__ __launch_bounds__(256) void k_main(const float* __restrict__ adj)
{
    extern __shared__ ull sPj[];     // [128][64]: j-major, 2 m per ull (64 KB)

    const int tid   = threadIdx.x;
    const int wid   = tid >> 5;
    const int lane  = tid & 31;
    const int combo = blockIdx.x >> 5;             // 0..7 : b*2 + jh
    const int blkc  = blockIdx.x & 31;             // 0..31
    const int b     = combo >> 1;
    const int jh    = combo & 1;
    const int i     = (blkc << 3) + wid;           // 0..255
    const int ig    = (b << 8) + i;
    const int j0    = jh << 7;
    const float* __restrict__ adjr = adj + (size_t)ig * Nv;

    // stage pj tile: contiguous 16384 floats -> flat float4 copy, 16 iters
    {
        const float4* __restrict__ src =
            (const float4*)(g_pj + ((size_t)((b << 8) + j0)) * Mv);
        float4* dst = (float4*)sPj;
        #pragma unroll
        for (int it = 0; it < 16; ++it)
            dst[(it << 8) + tid] = __ldg(src + (it << 8) + tid);
    }

    const float aii = __ldg(adjr + i);

    if (jh == 0) {      // one block per (b, i-group) does the adj reductions
        float4 s0 = __ldg((const float4*)adjr + lane);
        float4 s1 = __ldg((const float4*)adjr + 32 + lane);
        float rs = ((s0.x+s0.y)+(s0.z+s0.w)) + ((s1.x+s1.y)+(s1.z+s1.w));
        #pragma unroll
        for (int o = 16; o; o >>= 1) rs += __shfl_xor_sync(0xffffffffu, rs, o);
        if (lane == 0) {
            g_denom[ig] = fmaxf(rs, 1.0f);
            g_amask[ig] = rs - aii;
        }
    }

    const ull pi2a = *(const ull*)(g_pi + ig * Mv + (lane << 2));
    const ull pi2b = *(const ull*)(g_pi + ig * Mv + (lane << 2) + 2);
    __syncthreads();

    ull acc0 = 0, acc1 = 0;
    #pragma unroll 4
    for (int j = 0; j < 128; j += 4) {
        float4 av = __ldg((const float4*)adjr + ((j0 + j) >> 2));  // uniform
        #pragma unroll
        for (int t = 0; t < 4; ++t) {
            float a = (t == 0) ? av.x : (t == 1) ? av.y : (t == 2) ? av.z : av.w;
            ulonglong2 p = *(const ulonglong2*)(sPj + (size_t)(j + t) * 64 + (lane << 1));
            ull ap = pk2(a);
            fma2(acc0, ap, silu_h2(add2(pi2a, p.x)));
            fma2(acc1, ap, silu_h2(add2(pi2b, p.y)));
        }
    }

    // subtract diagonal if i falls in this block's j-range
    if ((i >> 7) == jh) {
        ulonglong2 p = *(const ulonglong2*)(sPj + (size_t)(i & 127) * 64 + (lane << 1));
        ull ap = pk2(-aii);
        fma2(acc0, ap, silu_h2(add2(pi2a, p.x)));
        fma2(acc1, ap, silu_h2(add2(pi2b, p.y)));
    }

    float* dst = (jh == 0) ? g_S0 : g_S1;
    *(ull*)(dst + ig * Mv + (lane << 2))     = acc0;
    *(ull*)(dst + ig * Mv + (lane << 2) + 2) = acc1;
}

// ---------------------------------------------------------------------------
// K3: chained GEMM epilogue. 128 blocks x 512 thr, 8 rows/block. (unchanged)
// ---------------------------------------------------------------------------
__global__ __launch_bounds__(512) void k_post(const float* __restrict__ W2,  const float* __restrict__ b2,
                                              const float* __restrict__ Wc1, const float* __restrict__ bc1,
                                              const float* __restrict__ Wc2, const float* __restrict__ bc2,
                                              float* __restrict__ out)
{
    __shared__ ull sIn[8][Mv];      // duplicated f32x2 packs of current rows
    __shared__ ull sP[4][8][64];    // k-split partial accumulators

    const int tid  = threadIdx.x;
    const int row0 = blockIdx.x << 3;
    const int kseg = tid >> 7;          // 0..3
    const int rowg = (tid >> 6) & 1;    // rows {rowg, +2, +4, +6}
    const int cp   = tid & 63;          // col pair
    const int rrow = tid >> 6;          // reduce: output row 0..7
    const int rc   = (tid & 63) << 1;   // reduce: output col (even)

    for (int idx = tid; idx < 8 * Mv; idx += 512)
        sIn[idx >> 7][idx & 127] =
            pk2(__ldg(g_S0 + row0 * Mv + idx) + __ldg(g_S1 + row0 * Mv + idx));
    __syncthreads();

    #pragma unroll 1
    for (int phase = 0; phase < 3; ++phase) {
        const float* W = (phase == 0) ? W2 : (phase == 1) ? Wc1 : Wc2;
        ull a0 = 0, a1 = 0, a2 = 0, a3 = 0;
        const ull* __restrict__ Wp = (const ull*)W + cp;
        #pragma unroll 8
        for (int kk = 0; kk < 32; ++kk) {
            const int k = (kseg << 5) + kk;
            ull wp = __ldg(Wp + (k << 6));
            fma2(a0, sIn[rowg    ][k], wp);
            fma2(a1, sIn[rowg + 2][k], wp);
            fma2(a2, sIn[rowg + 4][k], wp);
            fma2(a3, sIn[rowg + 6][k], wp);
        }
        sP[kseg][rowg    ][cp] = a0;
        sP[kseg][rowg + 2][cp] = a1;
        sP[kseg][rowg + 4][cp] = a2;
        sP[kseg][rowg + 6][cp] = a3;
        __syncthreads();

        float vx = 0.f, vy = 0.f;
        #pragma unroll
        for (int ks = 0; ks < 4; ++ks) {
            float px, py; upk2(sP[ks][rrow][tid & 63], px, py);
            vx += px; vy += py;
        }
        const int grow = row0 + rrow;
        if (phase == 0) {
            float am  = __ldg(g_amask + grow);
            float inv = __fdividef(1.0f, __ldg(g_denom + grow));
            float2 bb = __ldg((const float2*)(b2 + rc));
            sIn[rrow][rc]     = pk2(fmaf(bb.x, am, vx) * inv);
            sIn[rrow][rc + 1] = pk2(fmaf(bb.y, am, vy) * inv);
        } else if (phase == 1) {
            float2 bb = __ldg((const float2*)(bc1 + rc));
            sIn[rrow][rc]     = pk2(silu_h(0.5f * (vx + bb.x)));
            sIn[rrow][rc + 1] = pk2(silu_h(0.5f * (vy + bb.y)));
        } else {
            float2 bb = __ldg((const float2*)(bc2 + rc));
            *(float2*)(out + grow * Cv + rc) = make_float2(vx + bb.x, vy + bb.y);
        }
        __syncthreads();
    }
}

// ---------------------------------------------------------------------------
// Launch. Inputs: 0:h 1:adj 2:W1a 3:W1b 4:b1 5:W2 6:b2 7:Wc1 8:bc1 9:Wc2 10:bc2
// ---------------------------------------------------------------------------
extern "C" void kernel_launch(void* const* d_in, const int* in_sizes, int n_in,
                              void* d_out, int out_size)
{
    (void)in_sizes; (void)n_in; (void)out_size;
    const float* h   = (const float*)d_in[0];
    const float* adj = (const float*)d_in[1];

    static bool attr_done = false;
    if (!attr_done) {
        cudaFuncSetAttribute(k_main, cudaFuncAttributeMaxDynamicSharedMemorySize, 65536);
        attr_done = true;
    }

    k_pre <<<256, 256>>>(h, (const float*)d_in[2], (const float*)d_in[3],
                         (const float*)d_in[4]);
    k_main<<<256, 256, 65536>>>(adj);
    k_post<<<128, 512>>>((const float*)d_in[5], (const float*)d_in[6],
                         (const float*)d_in[7], (const float*)d_in[8],
                         (const float*)d_in[9], (const float*)d_in[10],
                         (float*)d_out);
}